// round 1
// baseline (speedup 1.0000x reference)
#include <cuda_runtime.h>
#include <math.h>

#define BQ 2
#define CQ 80
#define HQ 32
#define WQ 88
#define PIX (HQ * WQ)          // 2816 pixels
#define NPTS 262144            // 128*128*16 points per batch
#define PTS_PER_BLK 64
#define THREADS 256
#define CG 20                  // 80 channels = 20 float4 groups
#define ITEMS (PTS_PER_BLK * CG)   // 1280 work items per block

// Transposed features: (B, H*W, C) so channels are contiguous per pixel.
__device__ float g_featT[BQ * PIX * CQ];
// Combined 3x4 projection matrix per batch: F = (intr*scale) * extr * bda
__device__ float g_F[BQ][12];

__global__ void prep_kernel(const float* __restrict__ feat,
                            const float* __restrict__ intrin,
                            const float* __restrict__ extrin,
                            const float* __restrict__ bda) {
    int i = blockIdx.x * blockDim.x + threadIdx.x;
    if (i < BQ * PIX * CQ) {
        int c = i % CQ;
        int rest = i / CQ;
        int pix = rest % PIX;
        int b = rest / PIX;
        g_featT[i] = feat[((size_t)b * CQ + c) * PIX + pix];
    }
    if (blockIdx.x == 0 && threadIdx.x < BQ) {
        int b = threadIdx.x;
        const float* In = intrin + b * 16;  // (B,1,4,4)
        const float* Ex = extrin + b * 16;  // (B,1,4,4)
        const float* Bd = bda + b * 16;     // (B,4,4)
        // intrinsic = intrin[:3,:3] * scale (rows 0,1 by 1/8, row 2 by 1)
        // proj = intrinsic @ extrin[:3,:4]
        float P[3][4];
        for (int r = 0; r < 3; r++) {
            float s = (r < 2) ? 0.125f : 1.0f;
            for (int cc = 0; cc < 4; cc++) {
                float acc = 0.0f;
                for (int k = 0; k < 3; k++)
                    acc += In[r * 4 + k] * s * Ex[k * 4 + cc];
                P[r][cc] = acc;
            }
        }
        // F = proj @ bda  (3x4)
        for (int r = 0; r < 3; r++) {
            for (int cc = 0; cc < 4; cc++) {
                float acc = 0.0f;
                for (int k = 0; k < 4; k++)
                    acc += P[r][k] * Bd[k * 4 + cc];
                g_F[b][r * 4 + cc] = acc;
            }
        }
    }
}

__global__ void __launch_bounds__(THREADS)
bev_kernel(float* __restrict__ out) {
    __shared__ float s_w[4][PTS_PER_BLK];
    __shared__ int   s_idx[4][PTS_PER_BLK];
    __shared__ float s_out[PTS_PER_BLK][CQ + 1];  // stride 81: breaks bank conflicts

    const int bidx = blockIdx.x;
    const int b = bidx >> 12;                 // 4096 blocks per batch
    const int nbase = (bidx & 4095) * PTS_PER_BLK;
    const int tid = threadIdx.x;

    // ---- Phase A: geometry for 64 points ----
    if (tid < PTS_PER_BLK) {
        int n = nbase + tid;
        int ix = n >> 11;            // NY*NZ = 2048
        int iy = (n >> 4) & 127;     // NZ = 16
        int iz = n & 15;
        float X = -51.2f + ix * 0.8f;
        float Y = -51.2f + iy * 0.8f;
        float Z = -5.0f + iz * 0.5f;
        const float* F = g_F[b];
        float px = F[0] * X + F[1] * Y + F[2]  * Z + F[3];
        float py = F[4] * X + F[5] * Y + F[6]  * Z + F[7];
        float pz = F[8] * X + F[9] * Y + F[10] * Z + F[11];
        float u = px / pz;
        float v = py / pz;
        u = u / (float)WQ * 2.0f - 1.0f;
        v = v / (float)HQ * 2.0f - 1.0f;
        float x = (u + 1.0f) * 0.5f * (float)(WQ - 1);
        float y = (v + 1.0f) * 0.5f * (float)(HQ - 1);
        if (!(isfinite(x) && isfinite(y))) { x = -10.0f; y = -10.0f; }
        float x0f = floorf(x), y0f = floorf(y);
        float wx1 = x - x0f, wy1 = y - y0f;
        float wx0 = 1.0f - wx1, wy0 = 1.0f - wy1;
        float x1f = x0f + 1.0f, y1f = y0f + 1.0f;
        bool vx0 = (x0f >= 0.0f) && (x0f <= (float)(WQ - 1));
        bool vx1 = (x1f >= 0.0f) && (x1f <= (float)(WQ - 1));
        bool vy0 = (y0f >= 0.0f) && (y0f <= (float)(HQ - 1));
        bool vy1 = (y1f >= 0.0f) && (y1f <= (float)(HQ - 1));
        int xi0 = (int)fminf(fmaxf(x0f, 0.0f), (float)(WQ - 1));
        int xi1 = (int)fminf(fmaxf(x1f, 0.0f), (float)(WQ - 1));
        int yi0 = (int)fminf(fmaxf(y0f, 0.0f), (float)(HQ - 1));
        int yi1 = (int)fminf(fmaxf(y1f, 0.0f), (float)(HQ - 1));
        s_idx[0][tid] = yi0 * WQ + xi0;
        s_idx[1][tid] = yi0 * WQ + xi1;
        s_idx[2][tid] = yi1 * WQ + xi0;
        s_idx[3][tid] = yi1 * WQ + xi1;
        s_w[0][tid] = (vx0 && vy0) ? wx0 * wy0 : 0.0f;
        s_w[1][tid] = (vx1 && vy0) ? wx1 * wy0 : 0.0f;
        s_w[2][tid] = (vx0 && vy1) ? wx0 * wy1 : 0.0f;
        s_w[3][tid] = (vx1 && vy1) ? wx1 * wy1 : 0.0f;
    }
    __syncthreads();

    // ---- Phase B: gather + bilinear combine, channel-vectorized (float4) ----
    const float4* fT = (const float4*)(g_featT + (size_t)b * PIX * CQ);
    #pragma unroll
    for (int it = 0; it < ITEMS / THREADS; it++) {
        int i = it * THREADS + tid;   // 0..1279
        int p = i / CG;
        int g = i - p * CG;
        int i0 = s_idx[0][p] * CG + g;
        int i1 = s_idx[1][p] * CG + g;
        int i2 = s_idx[2][p] * CG + g;
        int i3 = s_idx[3][p] * CG + g;
        float w0 = s_w[0][p], w1 = s_w[1][p], w2 = s_w[2][p], w3 = s_w[3][p];
        float4 v0 = __ldg(&fT[i0]);
        float4 v1 = __ldg(&fT[i1]);
        float4 v2 = __ldg(&fT[i2]);
        float4 v3 = __ldg(&fT[i3]);
        float4 a;
        a.x = w0 * v0.x + w1 * v1.x + w2 * v2.x + w3 * v3.x;
        a.y = w0 * v0.y + w1 * v1.y + w2 * v2.y + w3 * v3.y;
        a.z = w0 * v0.z + w1 * v1.z + w2 * v2.z + w3 * v3.z;
        a.w = w0 * v0.w + w1 * v1.w + w2 * v2.w + w3 * v3.w;
        float* row = s_out[p];
        int c0 = g * 4;
        row[c0 + 0] = a.x;
        row[c0 + 1] = a.y;
        row[c0 + 2] = a.z;
        row[c0 + 3] = a.w;
    }
    __syncthreads();

    // ---- Phase C: transpose through SMEM, coalesced float4 stores along n ----
    float4* out4 = (float4*)out;
    #pragma unroll
    for (int it = 0; it < ITEMS / THREADS; it++) {
        int i = it * THREADS + tid;   // 0..1279
        int c = i >> 4;               // 80 channels
        int p4 = i & 15;              // 16 point-quads
        float4 r;
        r.x = s_out[4 * p4 + 0][c];
        r.y = s_out[4 * p4 + 1][c];
        r.z = s_out[4 * p4 + 2][c];
        r.w = s_out[4 * p4 + 3][c];
        size_t idx = (size_t)(b * CQ + c) * (NPTS / 4) + (nbase >> 2) + p4;
        out4[idx] = r;
    }
}

extern "C" void kernel_launch(void* const* d_in, const int* in_sizes, int n_in,
                              void* d_out, int out_size) {
    const float* img_feats = (const float*)d_in[0];
    const float* intrin    = (const float*)d_in[1];
    const float* extrin    = (const float*)d_in[2];
    const float* bda       = (const float*)d_in[3];
    float* out = (float*)d_out;

    int total = BQ * PIX * CQ;
    prep_kernel<<<(total + THREADS - 1) / THREADS, THREADS>>>(img_feats, intrin, extrin, bda);

    int nblocks = BQ * (NPTS / PTS_PER_BLK);   // 8192
    bev_kernel<<<nblocks, THREADS>>>(out);
}

// round 2
// speedup vs baseline: 1.0933x; 1.0933x over previous
#include <cuda_runtime.h>
#include <math.h>

#define BQ 2
#define CQ 80
#define HQ 32
#define WQ 88
#define PIX (HQ * WQ)          // 2816 pixels
#define NPTS 262144            // 128*128*16 points per batch
#define PTS_PER_BLK 64
#define THREADS 256
#define CG 20                  // 80 channels = 20 float4 groups
#define ITEMS (PTS_PER_BLK * CG)   // 1280 work items per block
#define SROW 21                // s_out row stride in float4 units (84 floats)

// Transposed features: (B, H*W, C) so channels are contiguous per pixel.
__device__ float g_featT[BQ * PIX * CQ];
// Combined 3x4 projection matrix per batch: F = (intr*scale) * extr * bda
__device__ float g_F[BQ][12];

// ---------------- prep: matrices ----------------
__global__ void mat_kernel(const float* __restrict__ intrin,
                           const float* __restrict__ extrin,
                           const float* __restrict__ bda) {
    int b = threadIdx.x;
    if (b >= BQ) return;
    const float* In = intrin + b * 16;
    const float* Ex = extrin + b * 16;
    const float* Bd = bda + b * 16;
    float P[3][4];
    for (int r = 0; r < 3; r++) {
        float s = (r < 2) ? 0.125f : 1.0f;
        for (int cc = 0; cc < 4; cc++) {
            float acc = 0.0f;
            for (int k = 0; k < 3; k++)
                acc += In[r * 4 + k] * s * Ex[k * 4 + cc];
            P[r][cc] = acc;
        }
    }
    for (int r = 0; r < 3; r++)
        for (int cc = 0; cc < 4; cc++) {
            float acc = 0.0f;
            for (int k = 0; k < 4; k++)
                acc += P[r][k] * Bd[k * 4 + cc];
            g_F[b][r * 4 + cc] = acc;
        }
}

// ---------------- prep: tiled transpose (B,C,HW) -> (B,HW,C) ----------------
__global__ void transpose_kernel(const float* __restrict__ feat) {
    __shared__ float tile[32][33];
    int b = blockIdx.z;
    int ct = blockIdx.y * 32;   // channel tile base
    int pt = blockIdx.x * 32;   // pixel tile base
    int tx = threadIdx.x, ty = threadIdx.y;   // (32,8)
    const float* src = feat + (size_t)b * CQ * PIX;
    #pragma unroll
    for (int j = 0; j < 32; j += 8) {
        int c = ct + ty + j;
        int p = pt + tx;
        if (c < CQ && p < PIX)
            tile[ty + j][tx] = src[(size_t)c * PIX + p];
    }
    __syncthreads();
    float* dst = g_featT + (size_t)b * PIX * CQ;
    #pragma unroll
    for (int j = 0; j < 32; j += 8) {
        int p = pt + ty + j;
        int c = ct + tx;
        if (c < CQ && p < PIX)
            dst[(size_t)p * CQ + c] = tile[tx][ty + j];
    }
}

// ---------------- main kernel ----------------
__global__ void __launch_bounds__(THREADS)
bev_kernel(float* __restrict__ out) {
    __shared__ float4 s_w4[PTS_PER_BLK];
    __shared__ int4   s_idx4[PTS_PER_BLK];       // pixel * CG (float4 group base)
    __shared__ float4 s_out4[PTS_PER_BLK * SROW]; // 64 rows x 84 floats

    const int bidx = blockIdx.x;
    const int b = bidx >> 12;                 // 4096 blocks per batch
    const int nbase = (bidx & 4095) * PTS_PER_BLK;
    const int tid = threadIdx.x;

    // ---- Phase A: geometry for 64 points ----
    if (tid < PTS_PER_BLK) {
        int n = nbase + tid;
        int ix = n >> 11;            // NY*NZ = 2048
        int iy = (n >> 4) & 127;     // NZ = 16
        int iz = n & 15;
        float X = -51.2f + ix * 0.8f;
        float Y = -51.2f + iy * 0.8f;
        float Z = -5.0f + iz * 0.5f;
        const float* F = g_F[b];
        float px = F[0] * X + F[1] * Y + F[2]  * Z + F[3];
        float py = F[4] * X + F[5] * Y + F[6]  * Z + F[7];
        float pz = F[8] * X + F[9] * Y + F[10] * Z + F[11];
        float u = px / pz;
        float v = py / pz;
        u = u / (float)WQ * 2.0f - 1.0f;
        v = v / (float)HQ * 2.0f - 1.0f;
        float x = (u + 1.0f) * 0.5f * (float)(WQ - 1);
        float y = (v + 1.0f) * 0.5f * (float)(HQ - 1);
        if (!(isfinite(x) && isfinite(y))) { x = -10.0f; y = -10.0f; }
        float x0f = floorf(x), y0f = floorf(y);
        float wx1 = x - x0f, wy1 = y - y0f;
        float wx0 = 1.0f - wx1, wy0 = 1.0f - wy1;
        float x1f = x0f + 1.0f, y1f = y0f + 1.0f;
        bool vx0 = (x0f >= 0.0f) && (x0f <= (float)(WQ - 1));
        bool vx1 = (x1f >= 0.0f) && (x1f <= (float)(WQ - 1));
        bool vy0 = (y0f >= 0.0f) && (y0f <= (float)(HQ - 1));
        bool vy1 = (y1f >= 0.0f) && (y1f <= (float)(HQ - 1));
        int xi0 = (int)fminf(fmaxf(x0f, 0.0f), (float)(WQ - 1));
        int xi1 = (int)fminf(fmaxf(x1f, 0.0f), (float)(WQ - 1));
        int yi0 = (int)fminf(fmaxf(y0f, 0.0f), (float)(HQ - 1));
        int yi1 = (int)fminf(fmaxf(y1f, 0.0f), (float)(HQ - 1));
        int4 id;
        id.x = (yi0 * WQ + xi0) * CG;
        id.y = (yi0 * WQ + xi1) * CG;
        id.z = (yi1 * WQ + xi0) * CG;
        id.w = (yi1 * WQ + xi1) * CG;
        s_idx4[tid] = id;
        float4 w;
        w.x = (vx0 && vy0) ? wx0 * wy0 : 0.0f;
        w.y = (vx1 && vy0) ? wx1 * wy0 : 0.0f;
        w.z = (vx0 && vy1) ? wx0 * wy1 : 0.0f;
        w.w = (vx1 && vy1) ? wx1 * wy1 : 0.0f;
        s_w4[tid] = w;
    }
    __syncthreads();

    // ---- Phase B: predicated gathers + bilinear combine (float4 channels) ----
    const float4* fT = (const float4*)(g_featT + (size_t)b * PIX * CQ);
    #pragma unroll
    for (int it = 0; it < ITEMS / THREADS; it++) {
        int i = it * THREADS + tid;   // 0..1279
        int p = i / CG;
        int g = i - p * CG;
        float4 w = s_w4[p];
        int4 id = s_idx4[p];
        float4 a = make_float4(0.f, 0.f, 0.f, 0.f);
        if (w.x != 0.0f) {
            float4 v = __ldg(&fT[id.x + g]);
            a.x += w.x * v.x; a.y += w.x * v.y; a.z += w.x * v.z; a.w += w.x * v.w;
        }
        if (w.y != 0.0f) {
            float4 v = __ldg(&fT[id.y + g]);
            a.x += w.y * v.x; a.y += w.y * v.y; a.z += w.y * v.z; a.w += w.y * v.w;
        }
        if (w.z != 0.0f) {
            float4 v = __ldg(&fT[id.z + g]);
            a.x += w.z * v.x; a.y += w.z * v.y; a.z += w.z * v.z; a.w += w.z * v.w;
        }
        if (w.w != 0.0f) {
            float4 v = __ldg(&fT[id.w + g]);
            a.x += w.w * v.x; a.y += w.w * v.y; a.z += w.w * v.z; a.w += w.w * v.w;
        }
        // XOR-swizzled column group so Phase C stays <=2-way conflicted
        int cg = g ^ ((p >> 2) & 3);
        s_out4[p * SROW + cg] = a;
    }
    __syncthreads();

    // ---- Phase C: transpose through SMEM, coalesced float4 stores along n ----
    const float* s_outf = (const float*)s_out4;
    float4* out4 = (float4*)out;
    #pragma unroll
    for (int it = 0; it < ITEMS / THREADS; it++) {
        int i = it * THREADS + tid;   // 0..1279
        int c = i >> 4;               // 80 channels
        int p4 = i & 15;              // 16 point-quads
        int col = ((c >> 2) ^ (p4 & 3)) * 4 + (c & 3);   // de-swizzle
        int base = p4 * 4 * (SROW * 4) + col;
        float4 r;
        r.x = s_outf[base + 0 * (SROW * 4)];
        r.y = s_outf[base + 1 * (SROW * 4)];
        r.z = s_outf[base + 2 * (SROW * 4)];
        r.w = s_outf[base + 3 * (SROW * 4)];
        size_t idx = (size_t)(b * CQ + c) * (NPTS / 4) + (nbase >> 2) + p4;
        out4[idx] = r;
    }
}

extern "C" void kernel_launch(void* const* d_in, const int* in_sizes, int n_in,
                              void* d_out, int out_size) {
    const float* img_feats = (const float*)d_in[0];
    const float* intrin    = (const float*)d_in[1];
    const float* extrin    = (const float*)d_in[2];
    const float* bda       = (const float*)d_in[3];
    float* out = (float*)d_out;

    mat_kernel<<<1, 32>>>(intrin, extrin, bda);
    dim3 tgrid((PIX + 31) / 32, (CQ + 31) / 32, BQ);
    transpose_kernel<<<tgrid, dim3(32, 8)>>>(img_feats);

    int nblocks = BQ * (NPTS / PTS_PER_BLK);   // 8192
    bev_kernel<<<nblocks, THREADS>>>(out);
}